// round 15
// baseline (speedup 1.0000x reference)
#include <cuda_runtime.h>

#define T_STEPS 2048
#define N_IN    512
#define N_OUT   512
#define N_OBS   256

// g_e4[t] = { x_t.x_{t+1}, x_t.x_{t+2}, x_t.x_{t+3}, x_t.x_{t+4} }, 0 when OOB.
// Padded region (t >= T) stays zero (static zero-init, never written).
__device__ float4 g_e4[T_STEPS + 8];

typedef unsigned long long u64;

__device__ __forceinline__ float warp_bfly(float v) {
#pragma unroll
    for (int o = 16; o > 0; o >>= 1)
        v += __shfl_xor_sync(0xffffffffu, v, o);
    return v;
}

// Packed f32x2 FMA (Blackwell FFMA2): d = a*b + c per 32-bit half
__device__ __forceinline__ u64 fma2(u64 a, u64 b, u64 c) {
    u64 d;
    asm("fma.rn.f32x2 %0, %1, %2, %3;" : "=l"(d) : "l"(a), "l"(b), "l"(c));
    return d;
}
__device__ __forceinline__ u64 bcast2(float x) {
    u64 d;
    asm("mov.b64 %0, {%1, %1};" : "=l"(d) : "f"(x));
    return d;
}
__device__ __forceinline__ float sum2(u64 v) {
    unsigned int lo, hi;
    asm("mov.b64 {%0, %1}, %2;" : "=r"(lo), "=r"(hi) : "l"(v));
    return __uint_as_float(lo) + __uint_as_float(hi);
}
__device__ __forceinline__ void load_row(u64* dst, const float* base_lane) {
#pragma unroll
    for (int g = 0; g < 4; g++) {
        const ulonglong2 L = *reinterpret_cast<const ulonglong2*>(base_lane + g * 128);
        dst[2 * g] = L.x; dst[2 * g + 1] = L.y;
    }
}

// ---------------- pre-kernel: e_k[t] = x_t . x_{t+k}, k=1..4 ----------------
__global__ void precompute_e_kernel(const float* __restrict__ X) {
    const int t    = blockIdx.x * 8 + (threadIdx.x >> 5);
    const int lane = threadIdx.x & 31;
    if (t >= T_STEPS) return;

    float4 xt[4];
#pragma unroll
    for (int g = 0; g < 4; g++)
        xt[g] = *reinterpret_cast<const float4*>(&X[t * N_IN + g * 128 + lane * 4]);

    float acc[4];
#pragma unroll
    for (int k = 1; k <= 4; k++) {
        const bool valid = (t + k) < T_STEPS;
        const int  tk    = valid ? (t + k) : (T_STEPS - 1);
        float p = 0.0f;
#pragma unroll
        for (int g = 0; g < 4; g++) {
            const float4 xk = *reinterpret_cast<const float4*>(&X[tk * N_IN + g * 128 + lane * 4]);
            p = fmaf(xt[g].x, xk.x, p); p = fmaf(xt[g].y, xk.y, p);
            p = fmaf(xt[g].z, xk.z, p); p = fmaf(xt[g].w, xk.w, p);
        }
        p = warp_bfly(p);
        acc[k - 1] = valid ? p : 0.0f;
    }
    if (lane == 0)
        g_e4[t] = make_float4(acc[0], acc[1], acc[2], acc[3]);
}

// ---------------- main scan: one warp per row, 2 warps/SMSP ----------------
// W = alpha * V.  s_u = fma(alpha_u, Q_u + A1, term1)
//   Q_u = V_{u-4} . x_u   (P produced at iter u-5, butterfly pipelined)
//   A-chain timing: consume A1 at top; A1<-A2; A2<-A3+beta*e2; A3<-A4+beta*e3;
//                   A4<-beta*e4  (each term ages exactly k iterations)
//   term1 = b_{u-1} * e_1[u-1]
//   Single x ring (depth 8): slot u&7 holds x_u. Dot uses slot (u+5)&7,
//   V update uses slot u&7, then slot u&7 refills with x_{u+8}.
__global__ __launch_bounds__(256, 1)
void circuit_scan_kernel(const float* __restrict__ X,
                         const float* __restrict__ W_init,
                         const float* __restrict__ theta,
                         const int*   __restrict__ obs,
                         float*       __restrict__ out)
{
    const int warp = blockIdx.x * 8 + (threadIdx.x >> 5);
    const int lane = threadIdx.x & 31;
    const int row  = warp;

    const float lr  = 1.0f / (float)N_IN;
    const float th0 = __ldg(&theta[0]) * lr;
    const float th1 = __ldg(&theta[1]) * lr;

    int start = 0, count = 0;
#pragma unroll 8
    for (int i = 0; i < N_OBS; i++) {
        const int v = __ldg(&obs[i]);
        start += (v <  row) ? 1 : 0;
        count += (v == row) ? 1 : 0;
    }

    const float* Xl = X + lane * 4;

    u64 V[8];
    load_row(V, &W_init[row * N_IN + lane * 4]);

    float alpha = 1.0f, term1 = 0.0f;
    float A1 = 0.0f, A2 = 0.0f, A3 = 0.0f, A4 = 0.0f;
    float pp3 = 0.f, pp4 = 0.f, pp5 = 0.f, pp6 = 0.f, pp7 = 0.f;

    // ---- prologue: u = 0..7 direct (dot fully-updated V with x_u) ----
#pragma unroll
    for (int u = 0; u < 8; u++) {
        u64 xu[8];
        load_row(xu, Xl + u * N_IN);

        u64 a0 = 0, a1 = 0;
#pragma unroll
        for (int g = 0; g < 4; g++) {
            a0 = fma2(V[2 * g],     xu[2 * g],     a0);
            a1 = fma2(V[2 * g + 1], xu[2 * g + 1], a1);
        }
        const float s = alpha * warp_bfly(sum2(a0) + sum2(a1));
        const float e = __expf(-s);
        const float y = __fdividef(1.0f, 1.0f + e);
        if (lane < count) out[u * N_OBS + start + lane] = y;

        const float b = th0 * y;
        const float a = fmaf(th1 * y, y, 1.0f);
        const float alpha_nx = alpha * a;
        const float beta = __fdividef(b, alpha_nx);
        alpha = alpha_nx;

        const float4 er = g_e4[u];
        term1 = b * er.x;                       // e1 -> s_{u+1}
        A1 = A2;                                // -> s_{u+1}
        A2 = A3 + beta * er.y;                  // e2 -> s_{u+2}
        A3 = A4 + beta * er.z;                  // e3 -> s_{u+3}
        A4 = beta * er.w;                       // e4 -> s_{u+4}

        // V += beta * x_u
        const u64 b2 = bcast2(beta);
#pragma unroll
        for (int p = 0; p < 8; p++) V[p] = fma2(b2, xu[p], V[p]);

        // P_u = V_{u+1} . x_{u+5}  (only u = 3..7 needed for priming)
        if (u >= 3) {
            u64 xg[8];
            load_row(xg, Xl + (u + 5) * N_IN);
            u64 w0 = 0, w1 = 0;
#pragma unroll
            for (int g = 0; g < 4; g++) {
                w0 = fma2(V[2 * g],     xg[2 * g],     w0);
                w1 = fma2(V[2 * g + 1], xg[2 * g + 1], w1);
            }
            const float p = sum2(w0) + sum2(w1);
            if (u == 3) pp3 = p;
            if (u == 4) pp4 = p;
            if (u == 5) pp5 = p;
            if (u == 6) pp6 = p;
            if (u == 7) pp7 = p;
        }
    }

    // ---- prime butterfly pipeline ----
    float Q = warp_bfly(pp3);                       // complete: feeds s_8
    float c4 = pp4;
    c4 += __shfl_xor_sync(~0u, c4, 8);  c4 += __shfl_xor_sync(~0u, c4, 16);
    c4 += __shfl_xor_sync(~0u, c4, 4);  c4 += __shfl_xor_sync(~0u, c4, 2);
    float c3 = pp5;
    c3 += __shfl_xor_sync(~0u, c3, 8);  c3 += __shfl_xor_sync(~0u, c3, 16);
    c3 += __shfl_xor_sync(~0u, c3, 4);
    float c2 = pp6;
    c2 += __shfl_xor_sync(~0u, c2, 8);  c2 += __shfl_xor_sync(~0u, c2, 16);
    float c1 = pp7;

    // ---- single x ring: slot k holds x_{8+k} at loop entry ----
    u64 xr[8][8];
#pragma unroll
    for (int k = 0; k < 8; k++)
        load_row(xr[k], Xl + (8 + k) * N_IN);

    float4 ecur = g_e4[8];
    float4 enxt = g_e4[9];

    // ---- main loop: u = 8 .. 2047, unroll 8 (static ring indexing) ----
    for (int ub = 8; ub < T_STEPS; ub += 8) {
#pragma unroll
        for (int j = 0; j < 8; j++) {
            const int u = ub + j;

            const float s = fmaf(alpha, Q + A1, term1);
            const float e = __expf(-s);
            const float y = __fdividef(1.0f, 1.0f + e);
            if (lane < count) out[u * N_OBS + start + lane] = y;

            const float b = th0 * y;
            const float a = fmaf(th1 * y, y, 1.0f);
            const float alpha_nx = alpha * a;
            const float beta = __fdividef(b, alpha_nx);
            alpha = alpha_nx;

            term1 = b * ecur.x;                 // e1 -> s_{u+1}
            A1 = A2;                            // -> s_{u+1}
            A2 = A3 + beta * ecur.y;            // e2 -> s_{u+2}
            A3 = A4 + beta * ecur.z;            // e3 -> s_{u+3}
            A4 = beta * ecur.w;                 // e4 -> s_{u+4}

            ecur = enxt;
            enxt = g_e4[u + 2];

            // V += beta * x_u  (slot j), fused with P_u = V_{u+1} . x_{u+5} (slot (j+5)&7)
            u64* xu = xr[j];
            u64* xg = xr[(j + 5) & 7];
            const u64 b2 = bcast2(beta);
            u64 w0 = 0, w1 = 0;
#pragma unroll
            for (int g = 0; g < 4; g++) {
                V[2 * g]     = fma2(b2, xu[2 * g],     V[2 * g]);
                V[2 * g + 1] = fma2(b2, xu[2 * g + 1], V[2 * g + 1]);
                w0 = fma2(V[2 * g],     xg[2 * g],     w0);
                w1 = fma2(V[2 * g + 1], xg[2 * g + 1], w1);
            }
            const float p = sum2(w0) + sum2(w1);

            // pipelined butterfly: operands >= 1 iteration old
            const float Qn  = c4 + __shfl_xor_sync(~0u, c4, 1);
            const float c4n = c3 + __shfl_xor_sync(~0u, c3, 2);
            const float c3n = c2 + __shfl_xor_sync(~0u, c2, 4);
            float t1 = c1 + __shfl_xor_sync(~0u, c1, 8);
            const float c2n = t1 + __shfl_xor_sync(~0u, t1, 16);
            Q = Qn; c4 = c4n; c3 = c3n; c2 = c2n; c1 = p;

            // refill slot j with x_{u+8} (clamped; tail feeds unused reductions)
            int tn = u + 8; if (tn > T_STEPS - 1) tn = T_STEPS - 1;
            load_row(xr[j], Xl + tn * N_IN);
        }
    }
}

extern "C" void kernel_launch(void* const* d_in, const int* in_sizes, int n_in,
                              void* d_out, int out_size)
{
    const float* X      = (const float*)d_in[0];   // [2048, 512]
    const float* W_init = (const float*)d_in[1];   // [512, 512]
    const float* theta  = (const float*)d_in[2];   // [2]
    const int*   obs    = (const int*)d_in[3];     // [256], sorted
    float*       out    = (float*)d_out;           // [2048, 256]

    (void)in_sizes; (void)n_in; (void)out_size;

    precompute_e_kernel<<<256, 256>>>(X);
    // 512 rows -> 512 warps -> 64 CTAs x 256 threads (8 warps/CTA, 2 warps/SMSP)
    circuit_scan_kernel<<<64, 256>>>(X, W_init, theta, obs, out);
}

// round 16
// speedup vs baseline: 1.0001x; 1.0001x over previous
#include <cuda_runtime.h>

#define T_STEPS 2048
#define N_IN    512
#define N_OUT   512
#define N_OBS   256

// g_e4[t] = { x_t.x_{t+1}, x_t.x_{t+2}, x_t.x_{t+3}, x_t.x_{t+4} }, 0 when OOB.
// Padded region (t >= T) stays zero (static zero-init, never written).
__device__ float4 g_e4[T_STEPS + 8];

typedef unsigned long long u64;

__device__ __forceinline__ float warp_bfly(float v) {
#pragma unroll
    for (int o = 16; o > 0; o >>= 1)
        v += __shfl_xor_sync(0xffffffffu, v, o);
    return v;
}

// Packed f32x2 FMA (Blackwell FFMA2): d = a*b + c per 32-bit half
__device__ __forceinline__ u64 fma2(u64 a, u64 b, u64 c) {
    u64 d;
    asm("fma.rn.f32x2 %0, %1, %2, %3;" : "=l"(d) : "l"(a), "l"(b), "l"(c));
    return d;
}
__device__ __forceinline__ u64 bcast2(float x) {
    u64 d;
    asm("mov.b64 %0, {%1, %1};" : "=l"(d) : "f"(x));
    return d;
}
__device__ __forceinline__ float sum2(u64 v) {
    unsigned int lo, hi;
    asm("mov.b64 {%0, %1}, %2;" : "=r"(lo), "=r"(hi) : "l"(v));
    return __uint_as_float(lo) + __uint_as_float(hi);
}
__device__ __forceinline__ void load_row(u64* dst, const float* base_lane) {
#pragma unroll
    for (int g = 0; g < 4; g++) {
        const ulonglong2 L = *reinterpret_cast<const ulonglong2*>(base_lane + g * 128);
        dst[2 * g] = L.x; dst[2 * g + 1] = L.y;
    }
}

// ---------------- pre-kernel: e_k[t] = x_t . x_{t+k}, k=1..4 ----------------
__global__ void precompute_e_kernel(const float* __restrict__ X) {
    const int t    = blockIdx.x * 8 + (threadIdx.x >> 5);
    const int lane = threadIdx.x & 31;
    if (t >= T_STEPS) return;

    float4 xt[4];
#pragma unroll
    for (int g = 0; g < 4; g++)
        xt[g] = *reinterpret_cast<const float4*>(&X[t * N_IN + g * 128 + lane * 4]);

    float acc[4];
#pragma unroll
    for (int k = 1; k <= 4; k++) {
        const bool valid = (t + k) < T_STEPS;
        const int  tk    = valid ? (t + k) : (T_STEPS - 1);
        float p = 0.0f;
#pragma unroll
        for (int g = 0; g < 4; g++) {
            const float4 xk = *reinterpret_cast<const float4*>(&X[tk * N_IN + g * 128 + lane * 4]);
            p = fmaf(xt[g].x, xk.x, p); p = fmaf(xt[g].y, xk.y, p);
            p = fmaf(xt[g].z, xk.z, p); p = fmaf(xt[g].w, xk.w, p);
        }
        p = warp_bfly(p);
        acc[k - 1] = valid ? p : 0.0f;
    }
    if (lane == 0)
        g_e4[t] = make_float4(acc[0], acc[1], acc[2], acc[3]);
}

// ---------------- main scan: one warp per row, 2 warps/SMSP ----------------
// W = alpha * V.  s_u = fma(alpha_u, Q_u + A1, term1)
//   Q_u = V_{u-4} . x_u   (P produced at iter u-5, butterfly pipelined)
//   A-chain timing: consume A1 at top; A1<-A2; A2<-A3+beta*e2; A3<-A4+beta*e3;
//                   A4<-beta*e4  (each term ages exactly k iterations)
//   term1 = b_{u-1} * e_1[u-1]
//   Single x ring (depth 8): slot u&7 holds x_u. Dot uses slot (u+5)&7,
//   V update uses slot u&7, then slot u&7 refills with x_{u+8}.
__global__ __launch_bounds__(256, 1)
void circuit_scan_kernel(const float* __restrict__ X,
                         const float* __restrict__ W_init,
                         const float* __restrict__ theta,
                         const int*   __restrict__ obs,
                         float*       __restrict__ out)
{
    const int warp = blockIdx.x * 8 + (threadIdx.x >> 5);
    const int lane = threadIdx.x & 31;
    const int row  = warp;

    const float lr  = 1.0f / (float)N_IN;
    const float th0 = __ldg(&theta[0]) * lr;
    const float th1 = __ldg(&theta[1]) * lr;

    int start = 0, count = 0;
#pragma unroll 8
    for (int i = 0; i < N_OBS; i++) {
        const int v = __ldg(&obs[i]);
        start += (v <  row) ? 1 : 0;
        count += (v == row) ? 1 : 0;
    }

    const float* Xl = X + lane * 4;

    u64 V[8];
    load_row(V, &W_init[row * N_IN + lane * 4]);

    float alpha = 1.0f, term1 = 0.0f;
    float A1 = 0.0f, A2 = 0.0f, A3 = 0.0f, A4 = 0.0f;
    float pp3 = 0.f, pp4 = 0.f, pp5 = 0.f, pp6 = 0.f, pp7 = 0.f;

    // ---- prologue: u = 0..7 direct (dot fully-updated V with x_u) ----
#pragma unroll
    for (int u = 0; u < 8; u++) {
        u64 xu[8];
        load_row(xu, Xl + u * N_IN);

        u64 a0 = 0, a1 = 0;
#pragma unroll
        for (int g = 0; g < 4; g++) {
            a0 = fma2(V[2 * g],     xu[2 * g],     a0);
            a1 = fma2(V[2 * g + 1], xu[2 * g + 1], a1);
        }
        const float s = alpha * warp_bfly(sum2(a0) + sum2(a1));
        const float e = __expf(-s);
        const float y = __fdividef(1.0f, 1.0f + e);
        if (lane < count) out[u * N_OBS + start + lane] = y;

        const float b = th0 * y;
        const float a = fmaf(th1 * y, y, 1.0f);
        const float alpha_nx = alpha * a;
        const float beta = __fdividef(b, alpha_nx);
        alpha = alpha_nx;

        const float4 er = g_e4[u];
        term1 = b * er.x;                       // e1 -> s_{u+1}
        A1 = A2;                                // -> s_{u+1}
        A2 = A3 + beta * er.y;                  // e2 -> s_{u+2}
        A3 = A4 + beta * er.z;                  // e3 -> s_{u+3}
        A4 = beta * er.w;                       // e4 -> s_{u+4}

        // V += beta * x_u
        const u64 b2 = bcast2(beta);
#pragma unroll
        for (int p = 0; p < 8; p++) V[p] = fma2(b2, xu[p], V[p]);

        // P_u = V_{u+1} . x_{u+5}  (only u = 3..7 needed for priming)
        if (u >= 3) {
            u64 xg[8];
            load_row(xg, Xl + (u + 5) * N_IN);
            u64 w0 = 0, w1 = 0;
#pragma unroll
            for (int g = 0; g < 4; g++) {
                w0 = fma2(V[2 * g],     xg[2 * g],     w0);
                w1 = fma2(V[2 * g + 1], xg[2 * g + 1], w1);
            }
            const float p = sum2(w0) + sum2(w1);
            if (u == 3) pp3 = p;
            if (u == 4) pp4 = p;
            if (u == 5) pp5 = p;
            if (u == 6) pp6 = p;
            if (u == 7) pp7 = p;
        }
    }

    // ---- prime butterfly pipeline ----
    float Q = warp_bfly(pp3);                       // complete: feeds s_8
    float c4 = pp4;
    c4 += __shfl_xor_sync(~0u, c4, 8);  c4 += __shfl_xor_sync(~0u, c4, 16);
    c4 += __shfl_xor_sync(~0u, c4, 4);  c4 += __shfl_xor_sync(~0u, c4, 2);
    float c3 = pp5;
    c3 += __shfl_xor_sync(~0u, c3, 8);  c3 += __shfl_xor_sync(~0u, c3, 16);
    c3 += __shfl_xor_sync(~0u, c3, 4);
    float c2 = pp6;
    c2 += __shfl_xor_sync(~0u, c2, 8);  c2 += __shfl_xor_sync(~0u, c2, 16);
    float c1 = pp7;

    // ---- single x ring: slot k holds x_{8+k} at loop entry ----
    u64 xr[8][8];
#pragma unroll
    for (int k = 0; k < 8; k++)
        load_row(xr[k], Xl + (8 + k) * N_IN);

    float4 ecur = g_e4[8];
    float4 enxt = g_e4[9];

    // ---- main loop: u = 8 .. 2047, unroll 8 (static ring indexing) ----
    for (int ub = 8; ub < T_STEPS; ub += 8) {
#pragma unroll
        for (int j = 0; j < 8; j++) {
            const int u = ub + j;

            const float s = fmaf(alpha, Q + A1, term1);
            const float e = __expf(-s);
            const float y = __fdividef(1.0f, 1.0f + e);
            if (lane < count) out[u * N_OBS + start + lane] = y;

            const float b = th0 * y;
            const float a = fmaf(th1 * y, y, 1.0f);
            const float alpha_nx = alpha * a;
            const float beta = __fdividef(b, alpha_nx);
            alpha = alpha_nx;

            term1 = b * ecur.x;                 // e1 -> s_{u+1}
            A1 = A2;                            // -> s_{u+1}
            A2 = A3 + beta * ecur.y;            // e2 -> s_{u+2}
            A3 = A4 + beta * ecur.z;            // e3 -> s_{u+3}
            A4 = beta * ecur.w;                 // e4 -> s_{u+4}

            ecur = enxt;
            enxt = g_e4[u + 2];

            // V += beta * x_u  (slot j), fused with P_u = V_{u+1} . x_{u+5} (slot (j+5)&7)
            u64* xu = xr[j];
            u64* xg = xr[(j + 5) & 7];
            const u64 b2 = bcast2(beta);
            u64 w0 = 0, w1 = 0;
#pragma unroll
            for (int g = 0; g < 4; g++) {
                V[2 * g]     = fma2(b2, xu[2 * g],     V[2 * g]);
                V[2 * g + 1] = fma2(b2, xu[2 * g + 1], V[2 * g + 1]);
                w0 = fma2(V[2 * g],     xg[2 * g],     w0);
                w1 = fma2(V[2 * g + 1], xg[2 * g + 1], w1);
            }
            const float p = sum2(w0) + sum2(w1);

            // pipelined butterfly: operands >= 1 iteration old
            const float Qn  = c4 + __shfl_xor_sync(~0u, c4, 1);
            const float c4n = c3 + __shfl_xor_sync(~0u, c3, 2);
            const float c3n = c2 + __shfl_xor_sync(~0u, c2, 4);
            float t1 = c1 + __shfl_xor_sync(~0u, c1, 8);
            const float c2n = t1 + __shfl_xor_sync(~0u, t1, 16);
            Q = Qn; c4 = c4n; c3 = c3n; c2 = c2n; c1 = p;

            // refill slot j with x_{u+8} (clamped; tail feeds unused reductions)
            int tn = u + 8; if (tn > T_STEPS - 1) tn = T_STEPS - 1;
            load_row(xr[j], Xl + tn * N_IN);
        }
    }
}

extern "C" void kernel_launch(void* const* d_in, const int* in_sizes, int n_in,
                              void* d_out, int out_size)
{
    const float* X      = (const float*)d_in[0];   // [2048, 512]
    const float* W_init = (const float*)d_in[1];   // [512, 512]
    const float* theta  = (const float*)d_in[2];   // [2]
    const int*   obs    = (const int*)d_in[3];     // [256], sorted
    float*       out    = (float*)d_out;           // [2048, 256]

    (void)in_sizes; (void)n_in; (void)out_size;

    precompute_e_kernel<<<256, 256>>>(X);
    // 512 rows -> 512 warps -> 64 CTAs x 256 threads (8 warps/CTA, 2 warps/SMSP)
    circuit_scan_kernel<<<64, 256>>>(X, W_init, theta, obs, out);
}

// round 17
// speedup vs baseline: 1.0021x; 1.0020x over previous
#include <cuda_runtime.h>

#define T_STEPS 2048
#define N_IN    512
#define N_OUT   512
#define N_OBS   256

// g_e4[t] = { x_t.x_{t+1}, x_t.x_{t+2}, x_t.x_{t+3}, x_t.x_{t+4} }, 0 when OOB.
// Padded region (t >= T) stays zero (static zero-init, never written).
__device__ float4 g_e4[T_STEPS + 8];

typedef unsigned long long u64;

__device__ __forceinline__ float warp_bfly(float v) {
#pragma unroll
    for (int o = 16; o > 0; o >>= 1)
        v += __shfl_xor_sync(0xffffffffu, v, o);
    return v;
}

// Packed f32x2 FMA (Blackwell FFMA2): d = a*b + c per 32-bit half
__device__ __forceinline__ u64 fma2(u64 a, u64 b, u64 c) {
    u64 d;
    asm("fma.rn.f32x2 %0, %1, %2, %3;" : "=l"(d) : "l"(a), "l"(b), "l"(c));
    return d;
}
__device__ __forceinline__ u64 bcast2(float x) {
    u64 d;
    asm("mov.b64 %0, {%1, %1};" : "=l"(d) : "f"(x));
    return d;
}
__device__ __forceinline__ float sum2(u64 v) {
    unsigned int lo, hi;
    asm("mov.b64 {%0, %1}, %2;" : "=r"(lo), "=r"(hi) : "l"(v));
    return __uint_as_float(lo) + __uint_as_float(hi);
}
__device__ __forceinline__ void load_row(u64* dst, const float* base_lane) {
#pragma unroll
    for (int g = 0; g < 4; g++) {
        const ulonglong2 L = *reinterpret_cast<const ulonglong2*>(base_lane + g * 128);
        dst[2 * g] = L.x; dst[2 * g + 1] = L.y;
    }
}

// ---------------- pre-kernel: e_k[t] = x_t . x_{t+k}, k=1..4 ----------------
__global__ void precompute_e_kernel(const float* __restrict__ X) {
    const int t    = blockIdx.x * 8 + (threadIdx.x >> 5);
    const int lane = threadIdx.x & 31;
    if (t >= T_STEPS) return;

    float4 xt[4];
#pragma unroll
    for (int g = 0; g < 4; g++)
        xt[g] = *reinterpret_cast<const float4*>(&X[t * N_IN + g * 128 + lane * 4]);

    float acc[4];
#pragma unroll
    for (int k = 1; k <= 4; k++) {
        const bool valid = (t + k) < T_STEPS;
        const int  tk    = valid ? (t + k) : (T_STEPS - 1);
        float p = 0.0f;
#pragma unroll
        for (int g = 0; g < 4; g++) {
            const float4 xk = *reinterpret_cast<const float4*>(&X[tk * N_IN + g * 128 + lane * 4]);
            p = fmaf(xt[g].x, xk.x, p); p = fmaf(xt[g].y, xk.y, p);
            p = fmaf(xt[g].z, xk.z, p); p = fmaf(xt[g].w, xk.w, p);
        }
        p = warp_bfly(p);
        acc[k - 1] = valid ? p : 0.0f;
    }
    if (lane == 0)
        g_e4[t] = make_float4(acc[0], acc[1], acc[2], acc[3]);
}

// ---------------- main scan: one warp per row, 2 warps/SMSP ----------------
// W = alpha * V.  s_u = fma(alpha_u, Q_u + A1, term1)
//   Q_u = V_{u-4} . x_u   (P produced at iter u-5, butterfly pipelined)
//   A-chain timing: consume A1 at top; A1<-A2; A2<-A3+beta*e2; A3<-A4+beta*e3;
//                   A4<-beta*e4  (each term ages exactly k iterations)
//   term1 = b_{u-1} * e_1[u-1]
//   Single x ring (depth 8): slot u&7 holds x_u. Dot uses slot (u+5)&7,
//   V update uses slot u&7, then slot u&7 refills with x_{u+8}.
__global__ __launch_bounds__(256, 1)
void circuit_scan_kernel(const float* __restrict__ X,
                         const float* __restrict__ W_init,
                         const float* __restrict__ theta,
                         const int*   __restrict__ obs,
                         float*       __restrict__ out)
{
    const int warp = blockIdx.x * 8 + (threadIdx.x >> 5);
    const int lane = threadIdx.x & 31;
    const int row  = warp;

    const float lr  = 1.0f / (float)N_IN;
    const float th0 = __ldg(&theta[0]) * lr;
    const float th1 = __ldg(&theta[1]) * lr;

    int start = 0, count = 0;
#pragma unroll 8
    for (int i = 0; i < N_OBS; i++) {
        const int v = __ldg(&obs[i]);
        start += (v <  row) ? 1 : 0;
        count += (v == row) ? 1 : 0;
    }

    const float* Xl = X + lane * 4;

    u64 V[8];
    load_row(V, &W_init[row * N_IN + lane * 4]);

    float alpha = 1.0f, term1 = 0.0f;
    float A1 = 0.0f, A2 = 0.0f, A3 = 0.0f, A4 = 0.0f;
    float pp3 = 0.f, pp4 = 0.f, pp5 = 0.f, pp6 = 0.f, pp7 = 0.f;

    // ---- prologue: u = 0..7 direct (dot fully-updated V with x_u) ----
#pragma unroll
    for (int u = 0; u < 8; u++) {
        u64 xu[8];
        load_row(xu, Xl + u * N_IN);

        u64 a0 = 0, a1 = 0;
#pragma unroll
        for (int g = 0; g < 4; g++) {
            a0 = fma2(V[2 * g],     xu[2 * g],     a0);
            a1 = fma2(V[2 * g + 1], xu[2 * g + 1], a1);
        }
        const float s = alpha * warp_bfly(sum2(a0) + sum2(a1));
        const float e = __expf(-s);
        const float y = __fdividef(1.0f, 1.0f + e);
        if (lane < count) out[u * N_OBS + start + lane] = y;

        const float b = th0 * y;
        const float a = fmaf(th1 * y, y, 1.0f);
        const float alpha_nx = alpha * a;
        const float beta = __fdividef(b, alpha_nx);
        alpha = alpha_nx;

        const float4 er = g_e4[u];
        term1 = b * er.x;                       // e1 -> s_{u+1}
        A1 = A2;                                // -> s_{u+1}
        A2 = A3 + beta * er.y;                  // e2 -> s_{u+2}
        A3 = A4 + beta * er.z;                  // e3 -> s_{u+3}
        A4 = beta * er.w;                       // e4 -> s_{u+4}

        // V += beta * x_u
        const u64 b2 = bcast2(beta);
#pragma unroll
        for (int p = 0; p < 8; p++) V[p] = fma2(b2, xu[p], V[p]);

        // P_u = V_{u+1} . x_{u+5}  (only u = 3..7 needed for priming)
        if (u >= 3) {
            u64 xg[8];
            load_row(xg, Xl + (u + 5) * N_IN);
            u64 w0 = 0, w1 = 0;
#pragma unroll
            for (int g = 0; g < 4; g++) {
                w0 = fma2(V[2 * g],     xg[2 * g],     w0);
                w1 = fma2(V[2 * g + 1], xg[2 * g + 1], w1);
            }
            const float p = sum2(w0) + sum2(w1);
            if (u == 3) pp3 = p;
            if (u == 4) pp4 = p;
            if (u == 5) pp5 = p;
            if (u == 6) pp6 = p;
            if (u == 7) pp7 = p;
        }
    }

    // ---- prime butterfly pipeline ----
    float Q = warp_bfly(pp3);                       // complete: feeds s_8
    float c4 = pp4;
    c4 += __shfl_xor_sync(~0u, c4, 8);  c4 += __shfl_xor_sync(~0u, c4, 16);
    c4 += __shfl_xor_sync(~0u, c4, 4);  c4 += __shfl_xor_sync(~0u, c4, 2);
    float c3 = pp5;
    c3 += __shfl_xor_sync(~0u, c3, 8);  c3 += __shfl_xor_sync(~0u, c3, 16);
    c3 += __shfl_xor_sync(~0u, c3, 4);
    float c2 = pp6;
    c2 += __shfl_xor_sync(~0u, c2, 8);  c2 += __shfl_xor_sync(~0u, c2, 16);
    float c1 = pp7;

    // ---- single x ring: slot k holds x_{8+k} at loop entry ----
    u64 xr[8][8];
#pragma unroll
    for (int k = 0; k < 8; k++)
        load_row(xr[k], Xl + (8 + k) * N_IN);

    float4 ecur = g_e4[8];
    float4 enxt = g_e4[9];

    // ---- main loop: u = 8 .. 2047, unroll 8 (static ring indexing) ----
    for (int ub = 8; ub < T_STEPS; ub += 8) {
#pragma unroll
        for (int j = 0; j < 8; j++) {
            const int u = ub + j;

            const float s = fmaf(alpha, Q + A1, term1);
            const float e = __expf(-s);
            const float y = __fdividef(1.0f, 1.0f + e);
            if (lane < count) out[u * N_OBS + start + lane] = y;

            const float b = th0 * y;
            const float a = fmaf(th1 * y, y, 1.0f);
            const float alpha_nx = alpha * a;
            const float beta = __fdividef(b, alpha_nx);
            alpha = alpha_nx;

            term1 = b * ecur.x;                 // e1 -> s_{u+1}
            A1 = A2;                            // -> s_{u+1}
            A2 = A3 + beta * ecur.y;            // e2 -> s_{u+2}
            A3 = A4 + beta * ecur.z;            // e3 -> s_{u+3}
            A4 = beta * ecur.w;                 // e4 -> s_{u+4}

            ecur = enxt;
            enxt = g_e4[u + 2];

            // V += beta * x_u  (slot j), fused with P_u = V_{u+1} . x_{u+5} (slot (j+5)&7)
            u64* xu = xr[j];
            u64* xg = xr[(j + 5) & 7];
            const u64 b2 = bcast2(beta);
            u64 w0 = 0, w1 = 0;
#pragma unroll
            for (int g = 0; g < 4; g++) {
                V[2 * g]     = fma2(b2, xu[2 * g],     V[2 * g]);
                V[2 * g + 1] = fma2(b2, xu[2 * g + 1], V[2 * g + 1]);
                w0 = fma2(V[2 * g],     xg[2 * g],     w0);
                w1 = fma2(V[2 * g + 1], xg[2 * g + 1], w1);
            }
            const float p = sum2(w0) + sum2(w1);

            // pipelined butterfly: operands >= 1 iteration old
            const float Qn  = c4 + __shfl_xor_sync(~0u, c4, 1);
            const float c4n = c3 + __shfl_xor_sync(~0u, c3, 2);
            const float c3n = c2 + __shfl_xor_sync(~0u, c2, 4);
            float t1 = c1 + __shfl_xor_sync(~0u, c1, 8);
            const float c2n = t1 + __shfl_xor_sync(~0u, t1, 16);
            Q = Qn; c4 = c4n; c3 = c3n; c2 = c2n; c1 = p;

            // refill slot j with x_{u+8} (clamped; tail feeds unused reductions)
            int tn = u + 8; if (tn > T_STEPS - 1) tn = T_STEPS - 1;
            load_row(xr[j], Xl + tn * N_IN);
        }
    }
}

extern "C" void kernel_launch(void* const* d_in, const int* in_sizes, int n_in,
                              void* d_out, int out_size)
{
    const float* X      = (const float*)d_in[0];   // [2048, 512]
    const float* W_init = (const float*)d_in[1];   // [512, 512]
    const float* theta  = (const float*)d_in[2];   // [2]
    const int*   obs    = (const int*)d_in[3];     // [256], sorted
    float*       out    = (float*)d_out;           // [2048, 256]

    (void)in_sizes; (void)n_in; (void)out_size;

    precompute_e_kernel<<<256, 256>>>(X);
    // 512 rows -> 512 warps -> 64 CTAs x 256 threads (8 warps/CTA, 2 warps/SMSP)
    circuit_scan_kernel<<<64, 256>>>(X, W_init, theta, obs, out);
}